// round 3
// baseline (speedup 1.0000x reference)
#include <cuda_runtime.h>
#include <cuda_bf16.h>
#include <math.h>

// ---------------- problem constants (constexpr: no macro-collision hazard) ----------------
constexpr int kB    = 2;
constexpr int kC    = 512;
constexpr int kHW   = 4096;          // 64*64
constexpr int kG    = 32;
constexpr int kCPG  = kC / kG;       // 16
constexpr int kQKVC = 3 * kC;        // 1536
constexpr float kEPS = 1e-6f;

// ---------------- scratch (no allocs allowed) ----------------
__device__ float g_hn[(size_t)kB * kC * kHW];            // 16 MB
__device__ float g_qkv[(size_t)kB * kQKVC * kHW];        // 48 MB
__device__ float g_scores[(size_t)kB * kHW * kHW];       // 128 MB
__device__ float g_att[(size_t)kB * kC * kHW];           // 16 MB

// ---------------- GroupNorm ----------------
// One block per (b, g). Reduce 16*4096 = 65536 floats -> mean/var, write normalized.
__global__ void groupnorm_kernel(const float* __restrict__ x,
                                 const float* __restrict__ gamma,
                                 const float* __restrict__ beta,
                                 float* __restrict__ hn)
{
    const int bg = blockIdx.x;
    const int b  = bg / kG;
    const int g  = bg % kG;
    const size_t base = ((size_t)b * kC + (size_t)g * kCPG) * kHW;
    const float* xp = x + base;
    float* hp = hn + base;

    const int NELEM = kCPG * kHW;  // 65536
    float s = 0.f, ss = 0.f;
    for (int i = threadIdx.x; i < NELEM; i += blockDim.x) {
        float v = xp[i];
        s += v; ss += v * v;
    }
    __shared__ float sha[8], shb[8];
    for (int o = 16; o; o >>= 1) {
        s  += __shfl_xor_sync(0xffffffffu, s,  o);
        ss += __shfl_xor_sync(0xffffffffu, ss, o);
    }
    int w = threadIdx.x >> 5;
    if ((threadIdx.x & 31) == 0) { sha[w] = s; shb[w] = ss; }
    __syncthreads();
    if (threadIdx.x < 32) {
        s  = (threadIdx.x < 8) ? sha[threadIdx.x] : 0.f;
        ss = (threadIdx.x < 8) ? shb[threadIdx.x] : 0.f;
        for (int o = 4; o; o >>= 1) {
            s  += __shfl_xor_sync(0xffffffffu, s,  o);
            ss += __shfl_xor_sync(0xffffffffu, ss, o);
        }
        if (threadIdx.x == 0) { sha[0] = s; shb[0] = ss; }
    }
    __syncthreads();
    const float mean = sha[0] * (1.f / NELEM);
    const float var  = shb[0] * (1.f / NELEM) - mean * mean;
    const float rstd = rsqrtf(var + kEPS);

    for (int i = threadIdx.x; i < NELEM; i += blockDim.x) {
        int ch = g * kCPG + i / kHW;
        float v = (xp[i] - mean) * rstd;
        hp[i] = v * gamma[ch] + beta[ch];
    }
}

// ---------------- Softmax over rows of 4096 ----------------
__global__ void softmax_kernel(float* __restrict__ scores)
{
    float* row = scores + (size_t)blockIdx.x * kHW;
    const int t = threadIdx.x;            // 256 threads, 16 elems each
    float vals[16];
    float m = -INFINITY;
    #pragma unroll
    for (int i = 0; i < 16; i++) {
        vals[i] = row[t + i * 256];
        m = fmaxf(m, vals[i]);
    }
    __shared__ float sh[8];
    for (int o = 16; o; o >>= 1) m = fmaxf(m, __shfl_xor_sync(0xffffffffu, m, o));
    if ((t & 31) == 0) sh[t >> 5] = m;
    __syncthreads();
    if (t < 32) {
        m = (t < 8) ? sh[t] : -INFINITY;
        for (int o = 4; o; o >>= 1) m = fmaxf(m, __shfl_xor_sync(0xffffffffu, m, o));
        if (t == 0) sh[0] = m;
    }
    __syncthreads();
    m = sh[0];
    __syncthreads();

    float s = 0.f;
    #pragma unroll
    for (int i = 0; i < 16; i++) {
        vals[i] = __expf(vals[i] - m);
        s += vals[i];
    }
    for (int o = 16; o; o >>= 1) s += __shfl_xor_sync(0xffffffffu, s, o);
    if ((t & 31) == 0) sh[t >> 5] = s;
    __syncthreads();
    if (t < 32) {
        s = (t < 8) ? sh[t] : 0.f;
        for (int o = 4; o; o >>= 1) s += __shfl_xor_sync(0xffffffffu, s, o);
        if (t == 0) sh[0] = s;
    }
    __syncthreads();
    const float inv = 1.f / sh[0];
    #pragma unroll
    for (int i = 0; i < 16; i++) row[t + i * 256] = vals[i] * inv;
}

// ---------------- Generic tiled SGEMM ----------------
// Cc[M,N] = alpha * op(A)[M,K] * op(B)[K,N] + bias[m] + residual[m,n]
// op(A)[m,k] = TA ? Ap[k*lda + m] : Ap[m*lda + k]
// op(B)[k,n] = TB ? Bp[n*ldb + k] : Bp[k*ldb + n]
// Dims assumed divisible: M%64==0, N%64==0, K%16==0.
template<bool TA, bool TB>
__global__ __launch_bounds__(256) void gemm64(
    const float* __restrict__ Ap, const float* __restrict__ Bp,
    float* __restrict__ Cc, int M, int N, int K,
    int lda, int ldb, int ldc,
    const float* __restrict__ bias, float alpha,
    const float* __restrict__ residual)
{
    constexpr int BM = 64, BN = 64, BK = 16;
    __shared__ float As[BK][BM];
    __shared__ float Bs[BK][BN];

    const int bm = blockIdx.y * BM;
    const int bn = blockIdx.x * BN;
    const int tid = threadIdx.x;
    const int tx = tid & 15;      // 0..15
    const int ty = tid >> 4;      // 0..15

    float acc[4][4];
    #pragma unroll
    for (int i = 0; i < 4; i++)
        #pragma unroll
        for (int j = 0; j < 4; j++) acc[i][j] = 0.f;

    for (int k0 = 0; k0 < K; k0 += BK) {
        // --- load A tile (64 rows x 16 k) ---
        if (!TA) {
            #pragma unroll
            for (int i = 0; i < 4; i++) {
                int idx = tid + i * 256;
                int m = idx >> 4, k = idx & 15;
                As[k][m] = Ap[(size_t)(bm + m) * lda + (k0 + k)];
            }
        } else {
            #pragma unroll
            for (int i = 0; i < 4; i++) {
                int idx = tid + i * 256;
                int m = idx & 63, k = idx >> 6;
                As[k][m] = Ap[(size_t)(k0 + k) * lda + (bm + m)];
            }
        }
        // --- load B tile (16 k x 64 cols) ---
        if (!TB) {
            #pragma unroll
            for (int i = 0; i < 4; i++) {
                int idx = tid + i * 256;
                int n = idx & 63, k = idx >> 6;
                Bs[k][n] = Bp[(size_t)(k0 + k) * ldb + (bn + n)];
            }
        } else {
            #pragma unroll
            for (int i = 0; i < 4; i++) {
                int idx = tid + i * 256;
                int n = idx >> 4, k = idx & 15;
                Bs[k][n] = Bp[(size_t)(bn + n) * ldb + (k0 + k)];
            }
        }
        __syncthreads();

        #pragma unroll
        for (int kk = 0; kk < BK; kk++) {
            float4 av = *reinterpret_cast<const float4*>(&As[kk][ty * 4]);
            float4 bv = *reinterpret_cast<const float4*>(&Bs[kk][tx * 4]);
            float a0 = av.x, a1 = av.y, a2 = av.z, a3 = av.w;
            float b0 = bv.x, b1 = bv.y, b2 = bv.z, b3 = bv.w;
            acc[0][0] += a0 * b0; acc[0][1] += a0 * b1; acc[0][2] += a0 * b2; acc[0][3] += a0 * b3;
            acc[1][0] += a1 * b0; acc[1][1] += a1 * b1; acc[1][2] += a1 * b2; acc[1][3] += a1 * b3;
            acc[2][0] += a2 * b0; acc[2][1] += a2 * b1; acc[2][2] += a2 * b2; acc[2][3] += a2 * b3;
            acc[3][0] += a3 * b0; acc[3][1] += a3 * b1; acc[3][2] += a3 * b2; acc[3][3] += a3 * b3;
        }
        __syncthreads();
    }

    // --- epilogue ---
    #pragma unroll
    for (int i = 0; i < 4; i++) {
        int m = bm + ty * 4 + i;
        float bi = bias ? bias[m] : 0.f;
        size_t off = (size_t)m * ldc + bn + tx * 4;
        float4 r = make_float4(0.f, 0.f, 0.f, 0.f);
        if (residual) r = *reinterpret_cast<const float4*>(residual + off);
        float4 o;
        o.x = acc[i][0] * alpha + bi + r.x;
        o.y = acc[i][1] * alpha + bi + r.y;
        o.z = acc[i][2] * alpha + bi + r.z;
        o.w = acc[i][3] * alpha + bi + r.w;
        *reinterpret_cast<float4*>(Cc + off) = o;
    }
}

// ---------------- launch ----------------
extern "C" void kernel_launch(void* const* d_in, const int* in_sizes, int n_in,
                              void* d_out, int out_size)
{
    const float* x      = (const float*)d_in[0];
    const float* gamma  = (const float*)d_in[1];
    const float* beta   = (const float*)d_in[2];
    const float* qkv_w  = (const float*)d_in[3];
    const float* qkv_b  = (const float*)d_in[4];
    const float* proj_w = (const float*)d_in[5];
    const float* proj_b = (const float*)d_in[6];
    float* out = (float*)d_out;

    float *hn, *qkv, *scores, *att;
    cudaGetSymbolAddress((void**)&hn, g_hn);
    cudaGetSymbolAddress((void**)&qkv, g_qkv);
    cudaGetSymbolAddress((void**)&scores, g_scores);
    cudaGetSymbolAddress((void**)&att, g_att);

    const float scale = 0.044194173824159216f;  // 512^-0.5

    groupnorm_kernel<<<kB * kG, 256>>>(x, gamma, beta, hn);

    for (int b = 0; b < kB; b++) {
        const float* hnb = hn + (size_t)b * kC * kHW;
        float* qkvb = qkv + (size_t)b * kQKVC * kHW;

        // QKV: [1536,4096] = W[1536,512] @ hn[512,4096] + bias
        gemm64<false, false><<<dim3(kHW / 64, kQKVC / 64), 256>>>(
            qkv_w, hnb, qkvb, kQKVC, kHW, kC, kC, kHW, kHW, qkv_b, 1.f, nullptr);

        const float* q = qkvb;
        const float* k = qkvb + (size_t)kC * kHW;
        const float* v = qkvb + (size_t)2 * kC * kHW;
        float* sb = scores + (size_t)b * kHW * kHW;

        // scores: [4096,4096] = Q^T @ K, scaled
        gemm64<true, false><<<dim3(kHW / 64, kHW / 64), 256>>>(
            q, k, sb, kHW, kHW, kC, kHW, kHW, kHW, nullptr, scale, nullptr);

        softmax_kernel<<<kHW, 256>>>(sb);

        // out: [512,4096] = V @ P^T  (O[c,i] = sum_j V[c,j]*P[i,j])
        float* ab = att + (size_t)b * kC * kHW;
        gemm64<false, true><<<dim3(kHW / 64, kC / 64), 256>>>(
            v, sb, ab, kC, kHW, kHW, kHW, kHW, kHW, nullptr, 1.f, nullptr);

        // proj + residual: out = proj_w @ O + proj_b + x
        gemm64<false, false><<<dim3(kHW / 64, kC / 64), 256>>>(
            proj_w, ab, out + (size_t)b * kC * kHW, kC, kHW, kC,
            kC, kHW, kHW, proj_b, 1.f, x + (size_t)b * kC * kHW);
    }
}

// round 5
// speedup vs baseline: 4.0841x; 4.0841x over previous
#include <cuda_runtime.h>
#include <cstdint>
#include <math.h>

// ---------------- problem constants ----------------
constexpr int kB    = 2;
constexpr int kC    = 512;
constexpr int kHW   = 4096;
constexpr int kG    = 32;
constexpr int kCPG  = kC / kG;       // 16
constexpr float kEPS = 1e-6f;

// ---------------- scratch ----------------
__device__ float g_hnt[(size_t)kB * kHW * kC];        // hn transposed [b][p][c]
__device__ float g_qkt[(size_t)kB * kHW * 1024];      // q,k transposed [b][p][0:1024]
__device__ float g_v  [(size_t)kB * kC * kHW];        // v [b][c][p]
__device__ float g_scores[(size_t)kB * kHW * kHW];    // [b][i][j]
__device__ float g_attt[(size_t)kB * kHW * kC];       // att transposed [b][p][c]

// ---------------- GroupNorm (writes hn TRANSPOSED [p, c]) ----------------
__global__ void groupnorm_kernel(const float* __restrict__ x,
                                 const float* __restrict__ gamma,
                                 const float* __restrict__ beta,
                                 float* __restrict__ hnt)
{
    const int bg = blockIdx.x;
    const int b  = bg / kG;
    const int g  = bg % kG;
    const size_t xbase = ((size_t)b * kC + (size_t)g * kCPG) * kHW;
    const float* xp = x + xbase;

    const int NELEM = kCPG * kHW;  // 65536
    float s = 0.f, ss = 0.f;
    for (int i = threadIdx.x; i < NELEM; i += blockDim.x) {
        float v = xp[i];
        s += v; ss += v * v;
    }
    __shared__ float sha[8], shb[8];
    for (int o = 16; o; o >>= 1) {
        s  += __shfl_xor_sync(0xffffffffu, s,  o);
        ss += __shfl_xor_sync(0xffffffffu, ss, o);
    }
    int w = threadIdx.x >> 5;
    if ((threadIdx.x & 31) == 0) { sha[w] = s; shb[w] = ss; }
    __syncthreads();
    if (threadIdx.x < 32) {
        s  = (threadIdx.x < 8) ? sha[threadIdx.x] : 0.f;
        ss = (threadIdx.x < 8) ? shb[threadIdx.x] : 0.f;
        for (int o = 4; o; o >>= 1) {
            s  += __shfl_xor_sync(0xffffffffu, s,  o);
            ss += __shfl_xor_sync(0xffffffffu, ss, o);
        }
        if (threadIdx.x == 0) { sha[0] = s; shb[0] = ss; }
    }
    __syncthreads();
    const float mean = sha[0] * (1.f / NELEM);
    const float var  = shb[0] * (1.f / NELEM) - mean * mean;
    const float rstd = rsqrtf(var + kEPS);

    float* hb = hnt + (size_t)b * kHW * kC;
    for (int i = threadIdx.x; i < NELEM; i += blockDim.x) {
        int cl = i & 15, p = i >> 4;
        int ch = g * kCPG + cl;
        float v = (x[((size_t)b * kC + ch) * kHW + p] - mean) * rstd;
        hb[(size_t)p * kC + ch] = v * gamma[ch] + beta[ch];
    }
}

// ---------------- Softmax over rows of 4096 ----------------
__global__ void softmax_kernel(float* __restrict__ scores)
{
    float* row = scores + (size_t)blockIdx.x * kHW;
    const int t = threadIdx.x;
    float vals[16];
    float m = -INFINITY;
    #pragma unroll
    for (int i = 0; i < 16; i++) {
        vals[i] = row[t + i * 256];
        m = fmaxf(m, vals[i]);
    }
    __shared__ float sh[8];
    for (int o = 16; o; o >>= 1) m = fmaxf(m, __shfl_xor_sync(0xffffffffu, m, o));
    if ((t & 31) == 0) sh[t >> 5] = m;
    __syncthreads();
    if (t < 32) {
        m = (t < 8) ? sh[t] : -INFINITY;
        for (int o = 4; o; o >>= 1) m = fmaxf(m, __shfl_xor_sync(0xffffffffu, m, o));
        if (t == 0) sh[0] = m;
    }
    __syncthreads();
    m = sh[0];
    __syncthreads();
    float s = 0.f;
    #pragma unroll
    for (int i = 0; i < 16; i++) { vals[i] = __expf(vals[i] - m); s += vals[i]; }
    for (int o = 16; o; o >>= 1) s += __shfl_xor_sync(0xffffffffu, s, o);
    if ((t & 31) == 0) sh[t >> 5] = s;
    __syncthreads();
    if (t < 32) {
        s = (t < 8) ? sh[t] : 0.f;
        for (int o = 4; o; o >>= 1) s += __shfl_xor_sync(0xffffffffu, s, o);
        if (t == 0) sh[0] = s;
    }
    __syncthreads();
    const float inv = 1.f / sh[0];
    #pragma unroll
    for (int i = 0; i < 16; i++) row[t + i * 256] = vals[i] * inv;
}

// ---------------- tf32 mma.sync GEMM ----------------
// D[m,n] = alpha * sum_k A[m,k]*B[n,k] (+bias_m[m] +bias_n[n] +residual[m,n])
// A,B K-major fp32.  M,N multiples of 128, K multiple of 32.
// Block 128x128x32, 256 threads, 8 warps (2m x 4n), warp tile 64x32.

__device__ __forceinline__ uint32_t f2tf(float x) {
    uint32_t u;
    asm("cvt.rna.tf32.f32 %0, %1;" : "=r"(u) : "f"(x));
    return u;
}

#define MMA_TF32(d, a, b) \
    asm volatile("mma.sync.aligned.m16n8k8.row.col.f32.tf32.tf32.f32 " \
        "{%0,%1,%2,%3},{%4,%5,%6,%7},{%8,%9},{%0,%1,%2,%3};" \
        : "+f"((d)[0]), "+f"((d)[1]), "+f"((d)[2]), "+f"((d)[3]) \
        : "r"((a)[0]), "r"((a)[1]), "r"((a)[2]), "r"((a)[3]), \
          "r"((b)[0]), "r"((b)[1]))

constexpr int kStride = 36;              // floats per smem row (bank = 4g+t4, conflict-free)
constexpr int kBufFloats = 128 * kStride * 2;  // A + B per buffer = 9216
constexpr int kSmemBytes = kBufFloats * 2 * 4; // 73728

__global__ __launch_bounds__(256) void gemm_tc(
    const float* __restrict__ Ap, const float* __restrict__ Bp, float* __restrict__ Cc,
    int M, int N, int K, int lda, int ldb, int ldc,
    const float* __restrict__ bias_m, const float* __restrict__ bias_n,
    float alpha, const float* __restrict__ residual)
{
    extern __shared__ float sm[];
    const int tid  = threadIdx.x;
    const int lane = tid & 31;
    const int wid  = tid >> 5;
    const int wm   = wid >> 2;          // 0..1
    const int wn   = wid & 3;           // 0..3
    const int g    = lane >> 2;         // 0..7
    const int t4   = lane & 3;          // 0..3
    const int bm = blockIdx.y * 128;
    const int bn = blockIdx.x * 128;

    float acc[4][4][4];
    #pragma unroll
    for (int a = 0; a < 4; a++)
        #pragma unroll
        for (int b = 0; b < 4; b++)
            #pragma unroll
            for (int c = 0; c < 4; c++) acc[a][b][c] = 0.f;

    float4 pa[4], pb[4];
    const int nch = K >> 5;

    // per-thread tile mapping: idx = tid + 256*i -> row = idx>>3, jj = idx&7 (float4 along k)
    #pragma unroll
    for (int i = 0; i < 4; i++) {
        int idx = tid + (i << 8);
        int r = idx >> 3, jj = idx & 7;
        pa[i] = *reinterpret_cast<const float4*>(Ap + (size_t)(bm + r) * lda + (jj << 2));
        pb[i] = *reinterpret_cast<const float4*>(Bp + (size_t)(bn + r) * ldb + (jj << 2));
    }

    for (int ch = 0; ch < nch; ch++) {
        const int cur = ch & 1;
        // store prefetched tile into buffer `cur`
        {
            float* As = sm + cur * kBufFloats;
            float* Bs = As + 128 * kStride;
            #pragma unroll
            for (int i = 0; i < 4; i++) {
                int idx = tid + (i << 8);
                int r = idx >> 3, jj = idx & 7;
                uint4 ua, ub;
                ua.x = f2tf(pa[i].x); ua.y = f2tf(pa[i].y); ua.z = f2tf(pa[i].z); ua.w = f2tf(pa[i].w);
                ub.x = f2tf(pb[i].x); ub.y = f2tf(pb[i].y); ub.z = f2tf(pb[i].z); ub.w = f2tf(pb[i].w);
                *reinterpret_cast<uint4*>(As + r * kStride + (jj << 2)) = ua;
                *reinterpret_cast<uint4*>(Bs + r * kStride + (jj << 2)) = ub;
            }
        }
        __syncthreads();

        // prefetch next tile
        if (ch + 1 < nch) {
            const int k0 = (ch + 1) << 5;
            #pragma unroll
            for (int i = 0; i < 4; i++) {
                int idx = tid + (i << 8);
                int r = idx >> 3, jj = idx & 7;
                pa[i] = *reinterpret_cast<const float4*>(Ap + (size_t)(bm + r) * lda + k0 + (jj << 2));
                pb[i] = *reinterpret_cast<const float4*>(Bp + (size_t)(bn + r) * ldb + k0 + (jj << 2));
            }
        }

        // compute on buffer `cur`
        {
            const float* As = sm + cur * kBufFloats;
            const float* Bs = As + 128 * kStride;
            #pragma unroll
            for (int s = 0; s < 4; s++) {
                const int k8 = s << 3;
                uint32_t aF[4][4], bF[4][2];
                #pragma unroll
                for (int mt = 0; mt < 4; mt++) {
                    const int r = wm * 64 + mt * 16 + g;
                    aF[mt][0] = __float_as_uint(As[r * kStride + k8 + t4]);
                    aF[mt][1] = __float_as_uint(As[(r + 8) * kStride + k8 + t4]);
                    aF[mt][2] = __float_as_uint(As[r * kStride + k8 + t4 + 4]);
                    aF[mt][3] = __float_as_uint(As[(r + 8) * kStride + k8 + t4 + 4]);
                }
                #pragma unroll
                for (int nt = 0; nt < 4; nt++) {
                    const int r = wn * 32 + nt * 8 + g;
                    bF[nt][0] = __float_as_uint(Bs[r * kStride + k8 + t4]);
                    bF[nt][1] = __float_as_uint(Bs[r * kStride + k8 + t4 + 4]);
                }
                #pragma unroll
                for (int mt = 0; mt < 4; mt++)
                    #pragma unroll
                    for (int nt = 0; nt < 4; nt++)
                        MMA_TF32(acc[mt][nt], aF[mt], bF[nt]);
            }
        }
        __syncthreads();
    }

    // ---- epilogue ----
    #pragma unroll
    for (int mt = 0; mt < 4; mt++) {
        const int r0 = bm + wm * 64 + mt * 16 + g;
        const int r1 = r0 + 8;
        const float bm0 = bias_m ? bias_m[r0] : 0.f;
        const float bm1 = bias_m ? bias_m[r1] : 0.f;
        #pragma unroll
        for (int nt = 0; nt < 4; nt++) {
            const int c = bn + wn * 32 + nt * 8 + t4 * 2;
            float bn0 = 0.f, bn1 = 0.f;
            if (bias_n) { bn0 = bias_n[c]; bn1 = bias_n[c + 1]; }
            float2 o0, o1;
            o0.x = acc[mt][nt][0] * alpha + bm0 + bn0;
            o0.y = acc[mt][nt][1] * alpha + bm0 + bn1;
            o1.x = acc[mt][nt][2] * alpha + bm1 + bn0;
            o1.y = acc[mt][nt][3] * alpha + bm1 + bn1;
            const size_t off0 = (size_t)r0 * ldc + c;
            const size_t off1 = (size_t)r1 * ldc + c;
            if (residual) {
                float2 q0 = *reinterpret_cast<const float2*>(residual + off0);
                float2 q1 = *reinterpret_cast<const float2*>(residual + off1);
                o0.x += q0.x; o0.y += q0.y; o1.x += q1.x; o1.y += q1.y;
            }
            *reinterpret_cast<float2*>(Cc + off0) = o0;
            *reinterpret_cast<float2*>(Cc + off1) = o1;
        }
    }
}

// ---------------- launch ----------------
extern "C" void kernel_launch(void* const* d_in, const int* in_sizes, int n_in,
                              void* d_out, int out_size)
{
    const float* x      = (const float*)d_in[0];
    const float* gamma  = (const float*)d_in[1];
    const float* beta   = (const float*)d_in[2];
    const float* qkv_w  = (const float*)d_in[3];
    const float* qkv_b  = (const float*)d_in[4];
    const float* proj_w = (const float*)d_in[5];
    const float* proj_b = (const float*)d_in[6];
    float* out = (float*)d_out;

    float *hnt, *qkt, *v, *scores, *attt;
    cudaGetSymbolAddress((void**)&hnt, g_hnt);
    cudaGetSymbolAddress((void**)&qkt, g_qkt);
    cudaGetSymbolAddress((void**)&v, g_v);
    cudaGetSymbolAddress((void**)&scores, g_scores);
    cudaGetSymbolAddress((void**)&attt, g_attt);

    cudaFuncSetAttribute(gemm_tc, cudaFuncAttributeMaxDynamicSharedMemorySize, kSmemBytes);

    const float scale = 0.044194173824159216f;  // 512^-0.5

    groupnorm_kernel<<<kB * kG, 256>>>(x, gamma, beta, hnt);

    for (int b = 0; b < kB; b++) {
        const float* hb = hnt + (size_t)b * kHW * kC;
        float* qkb = qkt + (size_t)b * kHW * 1024;
        float* vb  = v + (size_t)b * kC * kHW;
        float* sb  = scores + (size_t)b * kHW * kHW;
        float* ab  = attt + (size_t)b * kHW * kC;

        // qk_t[p, o] = sum_c hn_t[p,c] * Wqk[o,c] + qkv_b[o]   (o in [0,1024))
        gemm_tc<<<dim3(1024 / 128, kHW / 128), 256, kSmemBytes>>>(
            hb, qkv_w, qkb, kHW, 1024, kC, kC, kC, 1024,
            nullptr, qkv_b, 1.f, nullptr);

        // v[c', p] = sum_c Wv[c',c] * hn_t[p,c] + qkv_b[1024+c']
        gemm_tc<<<dim3(kHW / 128, kC / 128), 256, kSmemBytes>>>(
            qkv_w + (size_t)1024 * kC, hb, vb, kC, kHW, kC, kC, kC, kHW,
            qkv_b + 1024, nullptr, 1.f, nullptr);

        // scores[i, j] = scale * sum_c q_t[i,c] * k_t[j,c]
        gemm_tc<<<dim3(kHW / 128, kHW / 128), 256, kSmemBytes>>>(
            qkb, qkb + 512, sb, kHW, kHW, kC, 1024, 1024, kHW,
            nullptr, nullptr, scale, nullptr);

        softmax_kernel<<<kHW, 256>>>(sb);

        // att_t[i, c'] = sum_j P[i,j] * v[c', j]
        gemm_tc<<<dim3(kC / 128, kHW / 128), 256, kSmemBytes>>>(
            sb, vb, ab, kHW, kC, kHW, kHW, kHW, kC,
            nullptr, nullptr, 1.f, nullptr);

        // out[o, p] = sum_c Pw[o,c] * att_t[p,c] + proj_b[o] + x[o,p]
        gemm_tc<<<dim3(kHW / 128, kC / 128), 256, kSmemBytes>>>(
            proj_w, ab, out + (size_t)b * kC * kHW, kC, kHW, kC, kC, kC, kHW,
            proj_b, nullptr, 1.f, x + (size_t)b * kC * kHW);
    }
}

// round 7
// speedup vs baseline: 6.6313x; 1.6237x over previous
#include <cuda_runtime.h>
#include <cuda_fp16.h>
#include <cstdint>
#include <math.h>

// ---------------- problem constants ----------------
constexpr int kB    = 2;
constexpr int kC    = 512;
constexpr int kHW   = 4096;
constexpr int kG    = 32;
constexpr int kCPG  = kC / kG;       // 16
constexpr float kEPS = 1e-6f;

// ---------------- scratch ----------------
__device__ __half g_hnt[(size_t)kB * kHW * kC];        // hn^T [b][p][c]      8 MB
__device__ __half g_qkt[(size_t)kB * kHW * 1024];      // q,k^T [b][p][0:1024] 16 MB
__device__ __half g_v  [(size_t)kB * kC * kHW];        // v [b][c][p]          8 MB
__device__ float  g_scores[(size_t)kB * kHW * kHW];    // [b][i][j]          128 MB
__device__ __half g_p  [(size_t)kB * kHW * kHW];       // softmax(scores)     64 MB
__device__ __half g_attt[(size_t)kB * kHW * kC];       // att^T [b][p][c]      8 MB
__device__ __half g_w16[1536 * 512 + 512 * 512];       // qkv_w + proj_w fp16

// ---------------- helpers ----------------
__device__ __forceinline__ uint32_t smem_u32(const void* p) {
    uint32_t a;
    asm("{ .reg .u64 t; cvta.to.shared.u64 t, %1; cvt.u32.u64 %0, t; }" : "=r"(a) : "l"(p));
    return a;
}

// ---------------- weight fp16 conversion ----------------
__global__ void convert_w_kernel(const float* __restrict__ qkv_w,
                                 const float* __restrict__ proj_w)
{
    const int n1 = 1536 * 512;
    const int n2 = 512 * 512;
    for (int i = blockIdx.x * blockDim.x + threadIdx.x; i < n1 + n2;
         i += gridDim.x * blockDim.x) {
        float v = (i < n1) ? qkv_w[i] : proj_w[i - n1];
        g_w16[i] = __float2half(v);
    }
}

// ---------------- GroupNorm (writes hn TRANSPOSED [p, c], fp16) ----------------
__global__ void groupnorm_kernel(const float* __restrict__ x,
                                 const float* __restrict__ gamma,
                                 const float* __restrict__ beta,
                                 __half* __restrict__ hnt)
{
    const int bg = blockIdx.x;
    const int b  = bg / kG;
    const int g  = bg % kG;
    const size_t xbase = ((size_t)b * kC + (size_t)g * kCPG) * kHW;
    const float* xp = x + xbase;

    const int NELEM = kCPG * kHW;  // 65536
    float s = 0.f, ss = 0.f;
    for (int i = threadIdx.x; i < NELEM; i += blockDim.x) {
        float v = xp[i];
        s += v; ss += v * v;
    }
    __shared__ float sha[8], shb[8];
    for (int o = 16; o; o >>= 1) {
        s  += __shfl_xor_sync(0xffffffffu, s,  o);
        ss += __shfl_xor_sync(0xffffffffu, ss, o);
    }
    int w = threadIdx.x >> 5;
    if ((threadIdx.x & 31) == 0) { sha[w] = s; shb[w] = ss; }
    __syncthreads();
    if (threadIdx.x < 32) {
        s  = (threadIdx.x < 8) ? sha[threadIdx.x] : 0.f;
        ss = (threadIdx.x < 8) ? shb[threadIdx.x] : 0.f;
        for (int o = 4; o; o >>= 1) {
            s  += __shfl_xor_sync(0xffffffffu, s,  o);
            ss += __shfl_xor_sync(0xffffffffu, ss, o);
        }
        if (threadIdx.x == 0) { sha[0] = s; shb[0] = ss; }
    }
    __syncthreads();
    const float mean = sha[0] * (1.f / NELEM);
    const float var  = shb[0] * (1.f / NELEM) - mean * mean;
    const float rstd = rsqrtf(var + kEPS);

    __half* hb = hnt + (size_t)b * kHW * kC;
    for (int i = threadIdx.x; i < NELEM; i += blockDim.x) {
        int cl = i & 15, p = i >> 4;
        int ch = g * kCPG + cl;
        float v = (x[((size_t)b * kC + ch) * kHW + p] - mean) * rstd;
        hb[(size_t)p * kC + ch] = __float2half(v * gamma[ch] + beta[ch]);
    }
}

// ---------------- Softmax: fp32 scores -> fp16 P ----------------
__global__ void softmax_kernel(const float* __restrict__ scores,
                               __half* __restrict__ P)
{
    const float* row = scores + (size_t)blockIdx.x * kHW;
    __half* prow = P + (size_t)blockIdx.x * kHW;
    const int t = threadIdx.x;
    float vals[16];
    float m = -INFINITY;
    #pragma unroll
    for (int i = 0; i < 16; i++) {
        vals[i] = row[t + i * 256];
        m = fmaxf(m, vals[i]);
    }
    __shared__ float sh[8];
    for (int o = 16; o; o >>= 1) m = fmaxf(m, __shfl_xor_sync(0xffffffffu, m, o));
    if ((t & 31) == 0) sh[t >> 5] = m;
    __syncthreads();
    if (t < 32) {
        m = (t < 8) ? sh[t] : -INFINITY;
        for (int o = 4; o; o >>= 1) m = fmaxf(m, __shfl_xor_sync(0xffffffffu, m, o));
        if (t == 0) sh[0] = m;
    }
    __syncthreads();
    m = sh[0];
    __syncthreads();
    float s = 0.f;
    #pragma unroll
    for (int i = 0; i < 16; i++) { vals[i] = __expf(vals[i] - m); s += vals[i]; }
    for (int o = 16; o; o >>= 1) s += __shfl_xor_sync(0xffffffffu, s, o);
    if ((t & 31) == 0) sh[t >> 5] = s;
    __syncthreads();
    if (t < 32) {
        s = (t < 8) ? sh[t] : 0.f;
        for (int o = 4; o; o >>= 1) s += __shfl_xor_sync(0xffffffffu, s, o);
        if (t == 0) sh[0] = s;
    }
    __syncthreads();
    const float inv = 1.f / sh[0];
    #pragma unroll
    for (int i = 0; i < 16; i++) prow[t + i * 256] = __float2half(vals[i] * inv);
}

// ---------------- fp16 mma.sync GEMM (ldmatrix + double buffer) ----------------
// D[m,n] = alpha * sum_k A[m,k]*B[n,k] (+bias_m[m] +bias_n[n] +residual[m,n])
// A,B K-major fp16.  M,N multiples of 128, K multiple of 32.
// Block 128x128x32, 256 threads, 8 warps (2m x 4n), warp tile 64x32.
// OUT_HALF: store __half output, else fp32 (+optional residual).

#define MMA_F16(d, a, b) \
    asm volatile("mma.sync.aligned.m16n8k16.row.col.f32.f16.f16.f32 " \
        "{%0,%1,%2,%3},{%4,%5,%6,%7},{%8,%9},{%0,%1,%2,%3};" \
        : "+f"((d)[0]), "+f"((d)[1]), "+f"((d)[2]), "+f"((d)[3]) \
        : "r"((a)[0]), "r"((a)[1]), "r"((a)[2]), "r"((a)[3]), \
          "r"((b)[0]), "r"((b)[1]))

#define LDSM_X4(r0, r1, r2, r3, addr) \
    asm volatile("ldmatrix.sync.aligned.m8n8.x4.shared.b16 {%0,%1,%2,%3}, [%4];" \
        : "=r"(r0), "=r"(r1), "=r"(r2), "=r"(r3) : "r"(addr))

#define LDSM_X2(r0, r1, addr) \
    asm volatile("ldmatrix.sync.aligned.m8n8.x2.shared.b16 {%0,%1}, [%4];" \
        : "=r"(r0), "=r"(r1) : "r"(addr))

constexpr int kStrideH = 40;  // halves per smem row (80B): ldmatrix phase groups 5r+c distinct mod 8

template<bool OUT_HALF>
__global__ __launch_bounds__(256, 2) void gemm_h(
    const __half* __restrict__ Ap, const __half* __restrict__ Bp, void* __restrict__ Cv,
    int M, int N, int K, int lda, int ldb, int ldc,
    const float* __restrict__ bias_m, const float* __restrict__ bias_n,
    float alpha, const float* __restrict__ residual)
{
    __shared__ __align__(16) __half smA[2][128 * kStrideH];
    __shared__ __align__(16) __half smB[2][128 * kStrideH];

    const int tid  = threadIdx.x;
    const int lane = tid & 31;
    const int wid  = tid >> 5;
    const int wm   = wid >> 2;          // 0..1
    const int wn   = wid & 3;           // 0..3
    const int g    = lane >> 2;         // 0..7
    const int t4   = lane & 3;          // 0..3
    const int bm = blockIdx.y * 128;
    const int bn = blockIdx.x * 128;

    const uint32_t aBase0 = smem_u32(smA[0]);
    const uint32_t aBase1 = smem_u32(smA[1]);
    const uint32_t bBase0 = smem_u32(smB[0]);
    const uint32_t bBase1 = smem_u32(smB[1]);

    // ldmatrix per-lane byte offsets (within a tile buffer)
    const uint32_t aLaneOff = (uint32_t)(((wm * 64 + (lane & 15)) * kStrideH + (((lane >> 4) & 1) << 3)) * 2);
    const uint32_t bLaneOff = (uint32_t)(((wn * 32 + (lane & 7)) * kStrideH + (((lane >> 3) & 1) << 3)) * 2);

    float acc[4][4][4];
    #pragma unroll
    for (int a = 0; a < 4; a++)
        #pragma unroll
        for (int b = 0; b < 4; b++)
            #pragma unroll
            for (int c = 0; c < 4; c++) acc[a][b][c] = 0.f;

    uint4 pa[2], pb[2];
    const int nch = K >> 5;

    // per-thread load mapping: idx = tid + 256*i -> r = idx>>2 (0..127), jj = idx&3 (16B chunk)
    #pragma unroll
    for (int i = 0; i < 2; i++) {
        int idx = tid + (i << 8);
        int r = idx >> 2, jj = idx & 3;
        pa[i] = *reinterpret_cast<const uint4*>(Ap + (size_t)(bm + r) * lda + (jj << 3));
        pb[i] = *reinterpret_cast<const uint4*>(Bp + (size_t)(bn + r) * ldb + (jj << 3));
    }

    for (int ch = 0; ch < nch; ch++) {
        const int cur = ch & 1;
        __half* As = smA[cur];
        __half* Bs = smB[cur];
        #pragma unroll
        for (int i = 0; i < 2; i++) {
            int idx = tid + (i << 8);
            int r = idx >> 2, jj = idx & 3;
            *reinterpret_cast<uint4*>(As + r * kStrideH + (jj << 3)) = pa[i];
            *reinterpret_cast<uint4*>(Bs + r * kStrideH + (jj << 3)) = pb[i];
        }
        __syncthreads();

        if (ch + 1 < nch) {
            const int k0 = (ch + 1) << 5;
            #pragma unroll
            for (int i = 0; i < 2; i++) {
                int idx = tid + (i << 8);
                int r = idx >> 2, jj = idx & 3;
                pa[i] = *reinterpret_cast<const uint4*>(Ap + (size_t)(bm + r) * lda + k0 + (jj << 3));
                pb[i] = *reinterpret_cast<const uint4*>(Bp + (size_t)(bn + r) * ldb + k0 + (jj << 3));
            }
        }

        const uint32_t aB = (cur ? aBase1 : aBase0) + aLaneOff;
        const uint32_t bB = (cur ? bBase1 : bBase0) + bLaneOff;
        #pragma unroll
        for (int s = 0; s < 2; s++) {
            const uint32_t kOfs = (uint32_t)(s << 5);   // 16 halves = 32B
            uint32_t aF[4][4], bF[4][2];
            #pragma unroll
            for (int mt = 0; mt < 4; mt++) {
                LDSM_X4(aF[mt][0], aF[mt][1], aF[mt][2], aF[mt][3],
                        aB + (uint32_t)(mt * 16 * kStrideH * 2) + kOfs);
            }
            #pragma unroll
            for (int nt = 0; nt < 4; nt++) {
                asm volatile("ldmatrix.sync.aligned.m8n8.x2.shared.b16 {%0,%1}, [%2];"
                    : "=r"(bF[nt][0]), "=r"(bF[nt][1])
                    : "r"(bB + (uint32_t)(nt * 8 * kStrideH * 2) + kOfs));
            }
            #pragma unroll
            for (int mt = 0; mt < 4; mt++)
                #pragma unroll
                for (int nt = 0; nt < 4; nt++)
                    MMA_F16(acc[mt][nt], aF[mt], bF[nt]);
        }
        __syncthreads();
    }

    // ---- epilogue ----
    #pragma unroll
    for (int mt = 0; mt < 4; mt++) {
        const int r0 = bm + wm * 64 + mt * 16 + g;
        const int r1 = r0 + 8;
        const float bm0 = bias_m ? bias_m[r0] : 0.f;
        const float bm1 = bias_m ? bias_m[r1] : 0.f;
        #pragma unroll
        for (int nt = 0; nt < 4; nt++) {
            const int c = bn + wn * 32 + nt * 8 + t4 * 2;
            float bn0 = 0.f, bn1 = 0.f;
            if (bias_n) { bn0 = bias_n[c]; bn1 = bias_n[c + 1]; }
            float o00 = acc[mt][nt][0] * alpha + bm0 + bn0;
            float o01 = acc[mt][nt][1] * alpha + bm0 + bn1;
            float o10 = acc[mt][nt][2] * alpha + bm1 + bn0;
            float o11 = acc[mt][nt][3] * alpha + bm1 + bn1;
            const size_t off0 = (size_t)r0 * ldc + c;
            const size_t off1 = (size_t)r1 * ldc + c;
            if (OUT_HALF) {
                __half* Cc = (__half*)Cv;
                *reinterpret_cast<__half2*>(Cc + off0) = __floats2half2_rn(o00, o01);
                *reinterpret_cast<__half2*>(Cc + off1) = __floats2half2_rn(o10, o11);
            } else {
                float* Cc = (float*)Cv;
                if (residual) {
                    float2 q0 = *reinterpret_cast<const float2*>(residual + off0);
                    float2 q1 = *reinterpret_cast<const float2*>(residual + off1);
                    o00 += q0.x; o01 += q0.y; o10 += q1.x; o11 += q1.y;
                }
                *reinterpret_cast<float2*>(Cc + off0) = make_float2(o00, o01);
                *reinterpret_cast<float2*>(Cc + off1) = make_float2(o10, o11);
            }
        }
    }
}

// ---------------- launch ----------------
extern "C" void kernel_launch(void* const* d_in, const int* in_sizes, int n_in,
                              void* d_out, int out_size)
{
    const float* x      = (const float*)d_in[0];
    const float* gamma  = (const float*)d_in[1];
    const float* beta   = (const float*)d_in[2];
    const float* qkv_w  = (const float*)d_in[3];
    const float* qkv_b  = (const float*)d_in[4];
    const float* proj_w = (const float*)d_in[5];
    const float* proj_b = (const float*)d_in[6];
    float* out = (float*)d_out;

    __half *hnt, *qkt, *v, *P, *attt, *w16;
    float *scores;
    cudaGetSymbolAddress((void**)&hnt, g_hnt);
    cudaGetSymbolAddress((void**)&qkt, g_qkt);
    cudaGetSymbolAddress((void**)&v, g_v);
    cudaGetSymbolAddress((void**)&scores, g_scores);
    cudaGetSymbolAddress((void**)&P, g_p);
    cudaGetSymbolAddress((void**)&attt, g_attt);
    cudaGetSymbolAddress((void**)&w16, g_w16);

    const __half* w16_qk   = w16;                          // rows [0,1024)  of qkv_w
    const __half* w16_v    = w16 + (size_t)1024 * kC;      // rows [1024,1536)
    const __half* w16_proj = w16 + (size_t)1536 * kC;      // proj_w

    const float scale = 0.044194173824159216f;  // 512^-0.5

    convert_w_kernel<<<256, 256>>>(qkv_w, proj_w);
    groupnorm_kernel<<<kB * kG, 256>>>(x, gamma, beta, hnt);

    for (int b = 0; b < kB; b++) {
        const __half* hb = hnt + (size_t)b * kHW * kC;
        __half* qkb = qkt + (size_t)b * kHW * 1024;
        __half* vb  = v + (size_t)b * kC * kHW;
        float*  sb  = scores + (size_t)b * kHW * kHW;
        __half* pb  = P + (size_t)b * kHW * kHW;
        __half* ab  = attt + (size_t)b * kHW * kC;

        // qk^T[p, o] = sum_c hn^T[p,c] * Wqk[o,c] + qkv_b[o]
        gemm_h<true><<<dim3(1024 / 128, kHW / 128), 256>>>(
            hb, w16_qk, qkb, kHW, 1024, kC, kC, kC, 1024,
            nullptr, qkv_b, 1.f, nullptr);

        // v[c', p] = sum_c Wv[c',c] * hn^T[p,c] + qkv_b[1024+c']
        gemm_h<true><<<dim3(kHW / 128, kC / 128), 256>>>(
            w16_v, hb, vb, kC, kHW, kC, kC, kC, kHW,
            qkv_b + 1024, nullptr, 1.f, nullptr);

        // scores[i, j] = scale * sum_c q^T[i,c] * k^T[j,c]   (fp32 out)
        gemm_h<false><<<dim3(kHW / 128, kHW / 128), 256>>>(
            qkb, qkb + 512, sb, kHW, kHW, kC, 1024, 1024, kHW,
            nullptr, nullptr, scale, nullptr);

        softmax_kernel<<<kHW, 256>>>(sb, pb);

        // att^T[i, c'] = sum_j P[i,j] * v[c', j]
        gemm_h<true><<<dim3(kC / 128, kHW / 128), 256>>>(
            pb, vb, ab, kHW, kC, kHW, kHW, kHW, kC,
            nullptr, nullptr, 1.f, nullptr);

        // out[o, p] = sum_c Pw[o,c] * att^T[p,c] + proj_b[o] + x[o,p]  (fp32 + residual)
        gemm_h<false><<<dim3(kHW / 128, kC / 128), 256>>>(
            w16_proj, ab, out + (size_t)b * kC * kHW, kC, kHW, kC, kC, kC, kHW,
            proj_b, nullptr, 1.f, x + (size_t)b * kC * kHW);
    }
}

// round 8
// speedup vs baseline: 9.0702x; 1.3678x over previous
#include <cuda_runtime.h>
#include <cuda_fp16.h>
#include <cstdint>
#include <math.h>

// ---------------- problem constants ----------------
constexpr int kB    = 2;
constexpr int kC    = 512;
constexpr int kHW   = 4096;
constexpr int kG    = 32;
constexpr int kCPG  = kC / kG;       // 16
constexpr float kEPS = 1e-6f;

// ---------------- scratch ----------------
__device__ __half g_hnt[(size_t)kB * kHW * kC];        // hn^T [b][p][c]        8 MB
__device__ __half g_qkt[(size_t)kB * kHW * 1024];      // q,k^T [b][p][0:1024] 16 MB
__device__ __half g_v  [(size_t)kB * kC * kHW];        // v [b][c][p]           8 MB
__device__ __half g_e  [(size_t)kB * kHW * kHW];       // exp(scores) fp16     64 MB
__device__ __half g_attt[(size_t)kB * kHW * kC];       // att^T [b][p][c]       8 MB
__device__ __half g_w16[1536 * 512 + 512 * 512];       // qkv_w + proj_w fp16
__device__ float  g_rowsum[(size_t)kB * kHW];          // softmax denominators

// ---------------- helpers ----------------
__device__ __forceinline__ uint32_t smem_u32(const void* p) {
    uint32_t a;
    asm("{ .reg .u64 t; cvta.to.shared.u64 t, %1; cvt.u32.u64 %0, t; }" : "=r"(a) : "l"(p));
    return a;
}
__device__ __forceinline__ void cpa16(uint32_t s, const __half* g) {
    asm volatile("cp.async.cg.shared.global [%0], [%1], 16;" :: "r"(s), "l"(g) : "memory");
}
#define CP_COMMIT() asm volatile("cp.async.commit_group;" ::: "memory")
#define CP_WAIT(n)  asm volatile("cp.async.wait_group %0;" :: "n"(n) : "memory")

// ---------------- weight fp16 conversion + rowsum zero ----------------
__global__ void convert_w_kernel(const float* __restrict__ qkv_w,
                                 const float* __restrict__ proj_w)
{
    const int n1 = 1536 * 512;
    const int n2 = 512 * 512;
    const int nr = kB * kHW;
    for (int i = blockIdx.x * blockDim.x + threadIdx.x; i < n1 + n2;
         i += gridDim.x * blockDim.x) {
        float v = (i < n1) ? qkv_w[i] : proj_w[i - n1];
        g_w16[i] = __float2half(v);
    }
    for (int i = blockIdx.x * blockDim.x + threadIdx.x; i < nr;
         i += gridDim.x * blockDim.x)
        g_rowsum[i] = 0.f;
}

// ---------------- GroupNorm (writes hn^T [p, c], fp16) ----------------
__global__ void groupnorm_kernel(const float* __restrict__ x,
                                 const float* __restrict__ gamma,
                                 const float* __restrict__ beta,
                                 __half* __restrict__ hnt)
{
    const int bg = blockIdx.x;
    const int b  = bg / kG;
    const int g  = bg % kG;
    const size_t xbase = ((size_t)b * kC + (size_t)g * kCPG) * kHW;
    const float* xp = x + xbase;

    const int NELEM = kCPG * kHW;  // 65536
    float s = 0.f, ss = 0.f;
    for (int i = threadIdx.x; i < NELEM; i += blockDim.x) {
        float v = xp[i];
        s += v; ss += v * v;
    }
    __shared__ float sha[8], shb[8];
    for (int o = 16; o; o >>= 1) {
        s  += __shfl_xor_sync(0xffffffffu, s,  o);
        ss += __shfl_xor_sync(0xffffffffu, ss, o);
    }
    int w = threadIdx.x >> 5;
    if ((threadIdx.x & 31) == 0) { sha[w] = s; shb[w] = ss; }
    __syncthreads();
    if (threadIdx.x < 32) {
        s  = (threadIdx.x < 8) ? sha[threadIdx.x] : 0.f;
        ss = (threadIdx.x < 8) ? shb[threadIdx.x] : 0.f;
        for (int o = 4; o; o >>= 1) {
            s  += __shfl_xor_sync(0xffffffffu, s,  o);
            ss += __shfl_xor_sync(0xffffffffu, ss, o);
        }
        if (threadIdx.x == 0) { sha[0] = s; shb[0] = ss; }
    }
    __syncthreads();
    const float mean = sha[0] * (1.f / NELEM);
    const float var  = shb[0] * (1.f / NELEM) - mean * mean;
    const float rstd = rsqrtf(var + kEPS);

    __half* hb = hnt + (size_t)b * kHW * kC;
    for (int i = threadIdx.x; i < NELEM; i += blockDim.x) {
        int cl = i & 15, p = i >> 4;
        int ch = g * kCPG + cl;
        float v = (x[((size_t)b * kC + ch) * kHW + p] - mean) * rstd;
        hb[(size_t)p * kC + ch] = __float2half(v * gamma[ch] + beta[ch]);
    }
}

// ---------------- fp16 mma.sync GEMM (cp.async 4-stage, z-batched) ----------------
// D[m,n] = f( alpha * sum_k A[m,k]*B[n,k] )
// MODE 0: fp32 out + bias_m + residual
// MODE 1: fp16 out + optional bias_m / bias_n
// MODE 2: fp16 out = exp(alpha*acc), atomicAdd row sums into rowsum[z*M + m]
// MODE 3: fp16 out = acc / rowsum[z*M + m]
// A,B K-major fp16. M,N mult of 128, K mult of 32. gridDim.z = batch.

#define MMA_F16(d, a, b) \
    asm volatile("mma.sync.aligned.m16n8k16.row.col.f32.f16.f16.f32 " \
        "{%0,%1,%2,%3},{%4,%5,%6,%7},{%8,%9},{%0,%1,%2,%3};" \
        : "+f"((d)[0]), "+f"((d)[1]), "+f"((d)[2]), "+f"((d)[3]) \
        : "r"((a)[0]), "r"((a)[1]), "r"((a)[2]), "r"((a)[3]), \
          "r"((b)[0]), "r"((b)[1]))

constexpr int kNS       = 4;
constexpr int kStrideH  = 40;                      // halves per smem row (80B)
constexpr int kTileHalf = 128 * kStrideH;          // 5120 halves per matrix tile
constexpr int kStageB   = kTileHalf * 2 * 2;       // A+B bytes per stage = 20480
constexpr int kSmemB    = kNS * kStageB;           // 81920

template<int MODE>
__global__ __launch_bounds__(256, 2) void gemm_h(
    const __half* __restrict__ Ap, const __half* __restrict__ Bp, void* __restrict__ Cv,
    int M, int N, int K, int lda, int ldb, int ldc,
    size_t sA, size_t sB, size_t sC,
    const float* __restrict__ bias_m, const float* __restrict__ bias_n,
    float alpha, const float* __restrict__ residual, size_t sRes,
    float* __restrict__ rowsum)
{
    extern __shared__ __align__(16) __half sm[];
    const int tid  = threadIdx.x;
    const int lane = tid & 31;
    const int wid  = tid >> 5;
    const int wm   = wid >> 2;          // 0..1
    const int wn   = wid & 3;           // 0..3
    const int g    = lane >> 2;         // 0..7
    const int t4   = lane & 3;          // 0..3
    const int bm = blockIdx.y * 128;
    const int bn = blockIdx.x * 128;
    const int z  = blockIdx.z;

    Ap += (size_t)z * sA;
    Bp += (size_t)z * sB;

    const uint32_t smBase = smem_u32(sm);
    // per-thread global-load coords: idx = tid + 256*i -> r = idx>>2 (0..127), jj = idx&3
    const int lr = tid >> 2;
    const int lj = tid & 3;

    auto issue = [&](int stage, int k0) {
        const uint32_t sb = smBase + stage * kStageB;
        #pragma unroll
        for (int i = 0; i < 2; i++) {
            int r = lr + (i << 6);      // +64 rows for second pass
            uint32_t so = (uint32_t)((r * kStrideH + (lj << 3)) * 2);
            cpa16(sb + so, Ap + (size_t)(bm + r) * lda + k0 + (lj << 3));
            cpa16(sb + (uint32_t)(kTileHalf * 2) + so,
                  Bp + (size_t)(bn + r) * ldb + k0 + (lj << 3));
        }
    };

    // ldmatrix per-lane byte offsets within a tile
    const uint32_t aLaneOff = (uint32_t)(((wm * 64 + (lane & 15)) * kStrideH + (((lane >> 4) & 1) << 3)) * 2);
    const uint32_t bLaneOff = (uint32_t)(((wn * 32 + (lane & 7)) * kStrideH + (((lane >> 3) & 1) << 3)) * 2);

    float acc[4][4][4];
    #pragma unroll
    for (int a = 0; a < 4; a++)
        #pragma unroll
        for (int b = 0; b < 4; b++)
            #pragma unroll
            for (int c = 0; c < 4; c++) acc[a][b][c] = 0.f;

    const int nch = K >> 5;

    #pragma unroll
    for (int s = 0; s < kNS - 1; s++) { issue(s, s << 5); CP_COMMIT(); }

    int cur = 0;
    for (int ch = 0; ch < nch; ch++) {
        CP_WAIT(kNS - 2);
        __syncthreads();

        const uint32_t aB = smBase + cur * kStageB + aLaneOff;
        const uint32_t bB = smBase + cur * kStageB + (uint32_t)(kTileHalf * 2) + bLaneOff;
        #pragma unroll
        for (int s = 0; s < 2; s++) {
            const uint32_t kOfs = (uint32_t)(s << 5);   // 16 halves = 32B
            uint32_t aF[4][4], bF[4][2];
            #pragma unroll
            for (int mt = 0; mt < 4; mt++) {
                asm volatile("ldmatrix.sync.aligned.m8n8.x4.shared.b16 {%0,%1,%2,%3}, [%4];"
                    : "=r"(aF[mt][0]), "=r"(aF[mt][1]), "=r"(aF[mt][2]), "=r"(aF[mt][3])
                    : "r"(aB + (uint32_t)(mt * 16 * kStrideH * 2) + kOfs));
            }
            #pragma unroll
            for (int nt = 0; nt < 4; nt++) {
                asm volatile("ldmatrix.sync.aligned.m8n8.x2.shared.b16 {%0,%1}, [%2];"
                    : "=r"(bF[nt][0]), "=r"(bF[nt][1])
                    : "r"(bB + (uint32_t)(nt * 8 * kStrideH * 2) + kOfs));
            }
            #pragma unroll
            for (int mt = 0; mt < 4; mt++)
                #pragma unroll
                for (int nt = 0; nt < 4; nt++)
                    MMA_F16(acc[mt][nt], aF[mt], bF[nt]);
        }

        const int nx = ch + kNS - 1;
        if (nx < nch) {
            int nstage = nx % kNS;
            issue(nstage, nx << 5);
            CP_COMMIT();
        }
        if (++cur == kNS) cur = 0;
    }

    // ---- epilogue ----
    __syncthreads();   // safe smem reuse
    float* rs = reinterpret_cast<float*>(sm);
    if (MODE == 2) {
        if (tid < 128) rs[tid] = 0.f;
        __syncthreads();
    }

    #pragma unroll
    for (int mt = 0; mt < 4; mt++) {
        const int r0l = wm * 64 + mt * 16 + g;
        const int r1l = r0l + 8;
        const int r0 = bm + r0l;
        const int r1 = bm + r1l;
        float bm0 = 0.f, bm1 = 0.f;
        if (MODE <= 1 && bias_m) { bm0 = bias_m[r0]; bm1 = bias_m[r1]; }
        float inv0 = 1.f, inv1 = 1.f;
        if (MODE == 3) {
            inv0 = 1.f / rowsum[(size_t)z * M + r0];
            inv1 = 1.f / rowsum[(size_t)z * M + r1];
        }
        float sum0 = 0.f, sum1 = 0.f;
        #pragma unroll
        for (int nt = 0; nt < 4; nt++) {
            const int c = bn + wn * 32 + nt * 8 + t4 * 2;
            float bn0 = 0.f, bn1 = 0.f;
            if (MODE <= 1 && bias_n) { bn0 = bias_n[c]; bn1 = bias_n[c + 1]; }
            float o00 = acc[mt][nt][0] * alpha + bm0 + bn0;
            float o01 = acc[mt][nt][1] * alpha + bm0 + bn1;
            float o10 = acc[mt][nt][2] * alpha + bm1 + bn0;
            float o11 = acc[mt][nt][3] * alpha + bm1 + bn1;
            const size_t off0 = (size_t)r0 * ldc + c;
            const size_t off1 = (size_t)r1 * ldc + c;
            if (MODE == 0) {
                float* Cc = (float*)Cv + (size_t)z * sC;
                if (residual) {
                    const float* res = residual + (size_t)z * sRes;
                    float2 q0 = *reinterpret_cast<const float2*>(res + off0);
                    float2 q1 = *reinterpret_cast<const float2*>(res + off1);
                    o00 += q0.x; o01 += q0.y; o10 += q1.x; o11 += q1.y;
                }
                *reinterpret_cast<float2*>(Cc + off0) = make_float2(o00, o01);
                *reinterpret_cast<float2*>(Cc + off1) = make_float2(o10, o11);
            } else {
                __half* Cc = (__half*)Cv + (size_t)z * sC;
                if (MODE == 2) {
                    o00 = __expf(o00); o01 = __expf(o01);
                    o10 = __expf(o10); o11 = __expf(o11);
                    sum0 += o00 + o01; sum1 += o10 + o11;
                } else if (MODE == 3) {
                    o00 *= inv0; o01 *= inv0; o10 *= inv1; o11 *= inv1;
                }
                *reinterpret_cast<__half2*>(Cc + off0) = __floats2half2_rn(o00, o01);
                *reinterpret_cast<__half2*>(Cc + off1) = __floats2half2_rn(o10, o11);
            }
        }
        if (MODE == 2) {
            atomicAdd(&rs[r0l], sum0);
            atomicAdd(&rs[r1l], sum1);
        }
    }
    if (MODE == 2) {
        __syncthreads();
        if (tid < 128)
            atomicAdd(&rowsum[(size_t)z * M + bm + tid], rs[tid]);
    }
}

// ---------------- launch ----------------
extern "C" void kernel_launch(void* const* d_in, const int* in_sizes, int n_in,
                              void* d_out, int out_size)
{
    const float* x      = (const float*)d_in[0];
    const float* gamma  = (const float*)d_in[1];
    const float* beta   = (const float*)d_in[2];
    const float* qkv_w  = (const float*)d_in[3];
    const float* qkv_b  = (const float*)d_in[4];
    const float* proj_w = (const float*)d_in[5];
    const float* proj_b = (const float*)d_in[6];
    float* out = (float*)d_out;

    __half *hnt, *qkt, *v, *E, *attt, *w16;
    float *rowsum;
    cudaGetSymbolAddress((void**)&hnt, g_hnt);
    cudaGetSymbolAddress((void**)&qkt, g_qkt);
    cudaGetSymbolAddress((void**)&v, g_v);
    cudaGetSymbolAddress((void**)&E, g_e);
    cudaGetSymbolAddress((void**)&attt, g_attt);
    cudaGetSymbolAddress((void**)&w16, g_w16);
    cudaGetSymbolAddress((void**)&rowsum, g_rowsum);

    const __half* w16_qk   = w16;                       // rows [0,1024) of qkv_w
    const __half* w16_v    = w16 + (size_t)1024 * kC;   // rows [1024,1536)
    const __half* w16_proj = w16 + (size_t)1536 * kC;   // proj_w

    cudaFuncSetAttribute(gemm_h<0>, cudaFuncAttributeMaxDynamicSharedMemorySize, kSmemB);
    cudaFuncSetAttribute(gemm_h<1>, cudaFuncAttributeMaxDynamicSharedMemorySize, kSmemB);
    cudaFuncSetAttribute(gemm_h<2>, cudaFuncAttributeMaxDynamicSharedMemorySize, kSmemB);
    cudaFuncSetAttribute(gemm_h<3>, cudaFuncAttributeMaxDynamicSharedMemorySize, kSmemB);

    const float scale = 0.044194173824159216f;  // 512^-0.5

    convert_w_kernel<<<256, 256>>>(qkv_w, proj_w);
    groupnorm_kernel<<<kB * kG, 256>>>(x, gamma, beta, hnt);

    const size_t sHnt = (size_t)kHW * kC;      // 4096*512
    const size_t sQkt = (size_t)kHW * 1024;
    const size_t sV   = (size_t)kC * kHW;
    const size_t sE   = (size_t)kHW * kHW;
    const size_t sAtt = (size_t)kHW * kC;
    const size_t sOut = (size_t)kC * kHW;

    // qk^T[p,o] = sum_c hn^T[p,c] * Wqk[o,c] + qkv_b[o]
    gemm_h<1><<<dim3(8, 32, kB), 256, kSmemB>>>(
        hnt, w16_qk, qkt, kHW, 1024, kC, kC, kC, 1024,
        sHnt, 0, sQkt, nullptr, qkv_b, 1.f, nullptr, 0, nullptr);

    // v[c',p] = sum_c Wv[c',c] * hn^T[p,c] + qkv_b[1024+c']
    gemm_h<1><<<dim3(32, 4, kB), 256, kSmemB>>>(
        w16_v, hnt, v, kC, kHW, kC, kC, kC, kHW,
        0, sHnt, sV, qkv_b + 1024, nullptr, 1.f, nullptr, 0, nullptr);

    // E[i,j] = exp(scale * sum_c q^T[i,c] * k^T[j,c]);  rowsum[i] += row partials
    gemm_h<2><<<dim3(32, 32, kB), 256, kSmemB>>>(
        qkt, qkt + 512, E, kHW, kHW, kC, 1024, 1024, kHW,
        sQkt, sQkt, sE, nullptr, nullptr, scale, nullptr, 0, rowsum);

    // att^T[i,c'] = (sum_j E[i,j] * v[c',j]) / rowsum[i]
    gemm_h<3><<<dim3(4, 32, kB), 256, kSmemB>>>(
        E, v, attt, kHW, kC, kHW, kHW, kHW, kC,
        sE, sV, sAtt, nullptr, nullptr, 1.f, nullptr, 0, rowsum);

    // out[o,p] = sum_c Pw[o,c] * att^T[p,c] + proj_b[o] + x[o,p]
    gemm_h<0><<<dim3(32, 4, kB), 256, kSmemB>>>(
        w16_proj, attt, out, kC, kHW, kC, kC, kC, kHW,
        0, sAtt, sOut, proj_b, nullptr, 1.f, x, sOut, nullptr);
}